// round 7
// baseline (speedup 1.0000x reference)
#include <cuda_runtime.h>
#include <cuda_bf16.h>
#include <math.h>

#define Bb 4
#define Nn 1024
#define Ee 256
#define Hh 8
#define Dd 32

// ---------------- scratch (device globals; referenced ONLY inside kernels) ----
__device__ float g_Wh[(size_t)Hh*Bb*Nn*Dd];        // [h][b][n][d]  4MB
__device__ float g_s1[Hh*Bb*Nn];
__device__ float g_s2[Hh*Bb*Nn];
__device__ float g_attn[(size_t)Hh*Bb*Nn*Nn];      // 134MB (GAT attn, then MHA probs)
__device__ float g_x1[Bb*Nn*Ee];                   // GAT residual output
__device__ float g_tA[Bb*Nn*Ee];
__device__ float g_tB[Bb*Nn*Ee];
__device__ float g_q[Bb*Nn*Ee];
__device__ float g_k[Bb*Nn*Ee];
__device__ float g_v[Bb*Nn*Ee];
__device__ float g_o[Bb*Nn*Ee];
__device__ float g_eout[(size_t)Bb*Nn*Nn];         // e_out staging
__device__ float g_xout[Bb*Nn*Ee];                 // x staging
__device__ float g_psum[64*Ee];
__device__ float g_psq [64*Ee];
__device__ float g_cmean[Bb*Ee];
__device__ float g_crstd[Bb*Ee];

// ---------------- helpers ----------------
__device__ __forceinline__ float blockReduceSum(float v, float* sm) {
    sm[threadIdx.x] = v; __syncthreads();
    #pragma unroll
    for (int s = 128; s > 0; s >>= 1) {
        if (threadIdx.x < s) sm[threadIdx.x] += sm[threadIdx.x + s];
        __syncthreads();
    }
    float r = sm[0]; __syncthreads();
    return r;
}
__device__ __forceinline__ float blockReduceMax(float v, float* sm) {
    sm[threadIdx.x] = v; __syncthreads();
    #pragma unroll
    for (int s = 128; s > 0; s >>= 1) {
        if (threadIdx.x < s) sm[threadIdx.x] = fmaxf(sm[threadIdx.x], sm[threadIdx.x + s]);
        __syncthreads();
    }
    float r = sm[0]; __syncthreads();
    return r;
}
// packed fp32x2 fma: acc.{lo,hi} += a.{lo,hi} * b.{lo,hi}   (FFMA2 on sm_103a)
__device__ __forceinline__ void ffma2(unsigned long long& acc,
                                      unsigned long long a, unsigned long long b) {
    asm("fma.rn.f32x2 %0, %1, %2, %0;" : "+l"(acc) : "l"(a), "l"(b));
}
__device__ __forceinline__ float f2sum(unsigned long long p) {
    return __uint_as_float((unsigned)(p & 0xffffffffu)) + __uint_as_float((unsigned)(p >> 32));
}

// ---------------- K1: Wh = x @ Wg (per head), s1/s2 reductions ----------------
__global__ void k_wh(const float* __restrict__ x, const float* __restrict__ Wg,
                     const float* __restrict__ a1, const float* __restrict__ a2) {
    int bn = blockIdx.x;              // b*N + n
    int b = bn >> 10, n = bn & 1023;
    int h = threadIdx.x >> 5, d = threadIdx.x & 31;
    __shared__ float xs[256];
    xs[threadIdx.x] = x[bn * 256 + threadIdx.x];
    __syncthreads();
    float acc = 0.f;
    const float* wp = Wg + h * 8192 + d;   // Wg[h][f][d]
    #pragma unroll 8
    for (int f = 0; f < 256; f++) acc = fmaf(xs[f], wp[f * 32], acc);
    g_Wh[((size_t)(h * Bb + b) * Nn + n) * 32 + d] = acc;
    float v1 = acc * a1[h * 32 + d];
    float v2 = acc * a2[h * 32 + d];
    #pragma unroll
    for (int o = 16; o > 0; o >>= 1) {
        v1 += __shfl_down_sync(0xffffffffu, v1, o);
        v2 += __shfl_down_sync(0xffffffffu, v2, o);
    }
    if (d == 0) {
        g_s1[(h * Bb + b) * Nn + n] = v1;
        g_s2[(h * Bb + b) * Nn + n] = v2;
    }
}

// ---------------- K2: GAT attention rows (all 8 heads) + fused e_out -----------
// grid = B*N blocks; block handles one (b,n) row for all heads.
__global__ void k_gat_attn(const int* __restrict__ adj, float* __restrict__ eout_dst) {
    int n = blockIdx.x & 1023;
    int b = blockIdx.x >> 10;
    int t = threadIdx.x;
    __shared__ float sm[256];
    const int* ap = adj + (size_t)(b * Nn + n) * Nn;
    int am[4];
    #pragma unroll
    for (int i = 0; i < 4; i++) am[i] = ap[t + i * 256];
    float esum[4] = {0.f, 0.f, 0.f, 0.f};

    for (int h = 0; h < 8; h++) {
        float s1v = g_s1[(h * Bb + b) * Nn + n];
        const float* s2p = g_s2 + (h * Bb + b) * Nn;
        float ev[4];
        float mx = -INFINITY;
        #pragma unroll
        for (int i = 0; i < 4; i++) {
            float e = s1v + s2p[t + i * 256];
            e = e >= 0.f ? e : 0.1f * e;
            if (am[i] <= 0) e = -9e15f;
            ev[i] = e;
            mx = fmaxf(mx, e);
        }
        mx = blockReduceMax(mx, sm);
        float s = 0.f;
        #pragma unroll
        for (int i = 0; i < 4; i++) { ev[i] = __expf(ev[i] - mx); s += ev[i]; }
        s = blockReduceSum(s, sm);
        float inv = 1.0f / s;
        float* op = g_attn + (size_t)((h * Bb + b) * Nn + n) * Nn;
        #pragma unroll
        for (int i = 0; i < 4; i++) {
            float p = ev[i] * inv;
            op[t + i * 256] = p;
            esum[i] += p;
        }
    }
    float* dst = eout_dst ? eout_dst : g_eout;
    #pragma unroll
    for (int i = 0; i < 4; i++)
        dst[((size_t)b * Nn + n) * Nn + t + i * 256] = esum[i] * 0.125f;
}

// ---------------- K4: AV GEMM: C[64x32] tile = P[64x1024] @ V[1024x32] ----------
// mode 0 (hp): B = g_Wh[h][b], epilogue leaky(0.01) + residual x -> g_x1
// mode 1 (pv): B = g_v slice h -> g_o
// grid (16 tiles, 4 b, 8 h) = 512 blocks, 256 threads; thread tile 4 rows x 2 cols,
// accumulators packed f32x2 over k-parity.
__global__ void k_av(const float* __restrict__ x, int mode) {
    __shared__ float As[64 * 34];   // [row][k]  8.5KB
    __shared__ float Ws[32 * 34];   // [d][k]    4.25KB
    int tile = blockIdx.x, b = blockIdx.y, h = blockIdx.z;
    int t = threadIdx.x;
    int tr = t >> 4;        // 0..15 -> rows tr*4 .. tr*4+3
    int tc = t & 15;        // cols tc*2, tc*2+1
    int n0 = tile * 64;
    const float* ap  = g_attn + ((size_t)(h * Bb + b) * Nn + n0) * Nn;
    const float* whp = g_Wh + (size_t)(h * Bb + b) * Nn * 32;

    unsigned long long acc2[4][2];
    #pragma unroll
    for (int r = 0; r < 4; r++) { acc2[r][0] = 0ull; acc2[r][1] = 0ull; }

    for (int ch = 0; ch < 32; ch++) {
        int m0 = ch * 32;
        #pragma unroll
        for (int i = 0; i < 8; i++) {
            int idx = i * 256 + t;
            int row = idx >> 5, k = idx & 31;
            As[row * 34 + k] = ap[(size_t)row * Nn + m0 + k];
        }
        #pragma unroll
        for (int i = 0; i < 4; i++) {
            int idx = i * 256 + t;
            int m = idx >> 5, d = idx & 31;
            Ws[d * 34 + m] = (mode == 0)
                ? whp[(m0 + m) * 32 + d]
                : g_v[((size_t)b * Nn + m0 + m) * 256 + h * 32 + d];
        }
        __syncthreads();
        #pragma unroll
        for (int k2 = 0; k2 < 16; k2++) {
            unsigned long long w0 = *(const unsigned long long*)&Ws[(tc * 2 + 0) * 34 + 2 * k2];
            unsigned long long w1 = *(const unsigned long long*)&Ws[(tc * 2 + 1) * 34 + 2 * k2];
            #pragma unroll
            for (int r = 0; r < 4; r++) {
                unsigned long long a = *(const unsigned long long*)&As[(tr * 4 + r) * 34 + 2 * k2];
                ffma2(acc2[r][0], a, w0);
                ffma2(acc2[r][1], a, w1);
            }
        }
        __syncthreads();
    }
    #pragma unroll
    for (int r = 0; r < 4; r++) {
        int n = n0 + tr * 4 + r;
        #pragma unroll
        for (int c = 0; c < 2; c++) {
            float v = f2sum(acc2[r][c]);
            int idx = (b * Nn + n) * 256 + h * 32 + tc * 2 + c;
            if (mode == 0) {
                v = v >= 0.f ? v : 0.01f * v;
                g_x1[idx] = x[idx] + v;
            } else {
                g_o[idx] = v;
            }
        }
    }
}

// ---------------- K5: row norm (_cnorm axis=2), ddof=1 ----------------
// sel=0: g_x1 -> g_tA ; sel=1: g_tB -> g_tA
__global__ void k_rownorm(int sel) {
    __shared__ float sm[256];
    const float* in = sel ? g_tB : g_x1;
    float* out = g_tA;
    int bn = blockIdx.x, t = threadIdx.x;
    float v = in[bn * 256 + t];
    float mean = blockReduceSum(v, sm) * (1.0f / 256.0f);
    float dd = v - mean;
    float var = blockReduceSum(dd * dd, sm) * (1.0f / 255.0f);
    out[bn * 256 + t] = dd / (sqrtf(var) + 1e-6f);
}

// ---------------- K6: column norm stats (over g_tA), split reduction ----------
__global__ void k_colpart() {
    int b = blockIdx.x >> 4, tl = blockIdx.x & 15;
    int e = threadIdx.x;
    float s = 0.f, sq = 0.f;
    const float* p = g_tA + ((size_t)b * Nn + tl * 64) * 256 + e;
    #pragma unroll 4
    for (int i = 0; i < 64; i++) {
        float v = p[i * 256];
        s += v; sq += v * v;
    }
    g_psum[blockIdx.x * 256 + e] = s;
    g_psq [blockIdx.x * 256 + e] = sq;
}
__global__ void k_colstats() {
    int b = blockIdx.x, e = threadIdx.x;
    float s = 0.f, sq = 0.f;
    #pragma unroll
    for (int t = 0; t < 16; t++) {
        s  += g_psum[(b * 16 + t) * 256 + e];
        sq += g_psq [(b * 16 + t) * 256 + e];
    }
    float mean = s * (1.0f / 1024.0f);
    float var = (sq - 1024.0f * mean * mean) * (1.0f / 1023.0f);
    var = fmaxf(var, 0.f);
    g_cmean[b * 256 + e] = mean;
    g_crstd[b * 256 + e] = 1.0f / (sqrtf(var) + 1e-6f);
}

// ---------------- K7: GEMM  C[M,256] = A'[M,256] @ W[256,256]^T + bias ---------
// normA: apply column-norm (A - cmean)*crstd during A load (fuses k_colapply)
// asel: 0=g_tA, 2=g_o, 3=Aext (srcLayout applies)
// csel: 0=g_tB, 1=g_q, 2=g_k, 3=g_v, 4=Cext (fallback g_xout if null)
// tile 32(m) x 64(n), grid (128, 4), 256 threads, thread tile 2x4.
__global__ void k_gemm(const float* __restrict__ Aext, const float* __restrict__ W,
                       const float* __restrict__ bias, float* __restrict__ Cext,
                       int asel, int csel, int srcLayout, int normA) {
    __shared__ float As[32 * 65];
    __shared__ float Ws[64 * 65];
    const float* A = (asel == 0) ? g_tA : (asel == 2) ? g_o : Aext;
    float* C = (csel == 0) ? g_tB : (csel == 1) ? g_q : (csel == 2) ? g_k :
               (csel == 3) ? g_v : (Cext ? Cext : g_xout);
    int m0 = blockIdx.x * 32, i0 = blockIdx.y * 64;
    int t = threadIdx.x;
    int tr = t >> 4, ti = t & 15;   // rows tr*2..+1, cols ti*4..+3
    float acc[2][4];
    #pragma unroll
    for (int a = 0; a < 2; a++)
        #pragma unroll
        for (int c = 0; c < 4; c++) acc[a][c] = 0.f;

    for (int kt = 0; kt < 256; kt += 64) {
        #pragma unroll
        for (int l = 0; l < 8; l++) {
            int idx = t + l * 256;
            int r = idx >> 6, k = idx & 63;
            int bn = m0 + r;
            int abase;
            if (srcLayout) { int b = bn >> 10, n = bn & 1023; abase = (n * Bb + b) * 256; }
            else abase = bn * 256;
            float v = A[abase + kt + k];
            if (normA) {
                int b = bn >> 10;
                v = (v - g_cmean[b * 256 + kt + k]) * g_crstd[b * 256 + kt + k];
            }
            As[r * 65 + k] = v;
        }
        #pragma unroll
        for (int l = 0; l < 16; l++) {
            int idx = t + l * 256;
            int r = idx >> 6, k = idx & 63;
            Ws[r * 65 + k] = W[(i0 + r) * 256 + kt + k];
        }
        __syncthreads();
        #pragma unroll
        for (int k = 0; k < 64; k++) {
            float a[2], w[4];
            #pragma unroll
            for (int rr = 0; rr < 2; rr++) a[rr] = As[(tr * 2 + rr) * 65 + k];
            #pragma unroll
            for (int ii = 0; ii < 4; ii++) w[ii] = Ws[(ti * 4 + ii) * 65 + k];
            #pragma unroll
            for (int rr = 0; rr < 2; rr++)
                #pragma unroll
                for (int ii = 0; ii < 4; ii++)
                    acc[rr][ii] = fmaf(a[rr], w[ii], acc[rr][ii]);
        }
        __syncthreads();
    }
    #pragma unroll
    for (int rr = 0; rr < 2; rr++)
        #pragma unroll
        for (int ii = 0; ii < 4; ii++)
            C[(m0 + tr * 2 + rr) * 256 + i0 + ti * 4 + ii] = acc[rr][ii] + bias[i0 + ti * 4 + ii];
}

// ---------------- K8: QK^T + fused softmax -> P (into g_attn) ------------------
// grid (64 panels of 16 q-rows, 4 b, 8 h), 256 threads.
__global__ void k_qk() {
    __shared__ float Qs[16 * 33];    // [row][d]
    __shared__ float Ks[32 * 68];    // [d][col] pad 4
    int t = threadIdx.x;
    int b = blockIdx.y, h = blockIdx.z;
    int q0 = blockIdx.x * 16;
    int row = t >> 4, cg = t & 15;

    #pragma unroll
    for (int i = 0; i < 2; i++) {
        int idx = i * 256 + t;
        int r = idx >> 5, d = idx & 31;
        Qs[r * 33 + d] = g_q[((size_t)b * Nn + q0 + r) * 256 + h * 32 + d];
    }
    __syncthreads();

    float s[64];
    for (int kt = 0; kt < 16; kt++) {
        #pragma unroll
        for (int i = 0; i < 8; i++) {
            int idx = i * 256 + t;
            int col = idx >> 5, d = idx & 31;
            Ks[d * 68 + col] = g_k[((size_t)b * Nn + kt * 64 + col) * 256 + h * 32 + d];
        }
        __syncthreads();
        float s0 = 0.f, s1 = 0.f, s2 = 0.f, s3 = 0.f;
        #pragma unroll
        for (int d = 0; d < 32; d++) {
            float qd = Qs[row * 33 + d];
            float4 kv = *(const float4*)&Ks[d * 68 + cg * 4];
            s0 = fmaf(qd, kv.x, s0);
            s1 = fmaf(qd, kv.y, s1);
            s2 = fmaf(qd, kv.z, s2);
            s3 = fmaf(qd, kv.w, s3);
        }
        s[kt * 4 + 0] = s0; s[kt * 4 + 1] = s1;
        s[kt * 4 + 2] = s2; s[kt * 4 + 3] = s3;
        __syncthreads();
    }

    const float scale = 0.17677669529663689f;  // 1/sqrt(32)
    float mx = -INFINITY;
    #pragma unroll
    for (int i = 0; i < 64; i++) { s[i] *= scale; mx = fmaxf(mx, s[i]); }
    #pragma unroll
    for (int o = 8; o > 0; o >>= 1) mx = fmaxf(mx, __shfl_xor_sync(0xffffffffu, mx, o));
    float sum = 0.f;
    #pragma unroll
    for (int i = 0; i < 64; i++) { s[i] = __expf(s[i] - mx); sum += s[i]; }
    #pragma unroll
    for (int o = 8; o > 0; o >>= 1) sum += __shfl_xor_sync(0xffffffffu, sum, o);
    float inv = 1.0f / sum;

    float* prow = g_attn + ((size_t)(h * Bb + b) * Nn + q0 + row) * Nn;
    #pragma unroll
    for (int kt = 0; kt < 16; kt++) {
        float4 v = make_float4(s[kt * 4] * inv, s[kt * 4 + 1] * inv,
                               s[kt * 4 + 2] * inv, s[kt * 4 + 3] * inv);
        *(float4*)&prow[kt * 64 + cg * 4] = v;
    }
}

// ---------------- launch ----------------
extern "C" void kernel_launch(void* const* d_in, const int* in_sizes, int n_in,
                              void* d_out, int out_size) {
    const float* x          = (const float*)d_in[0];   // (B,N,E)
    const float* src        = (const float*)d_in[1];   // (N,B,E)
    const int*   adj        = (const int*)  d_in[2];   // (B,N,N)
    const float* Wg         = (const float*)d_in[3];   // (H,E,D)
    const float* a1         = (const float*)d_in[4];   // (H,D)
    const float* a2         = (const float*)d_in[5];   // (H,D)
    const float* lin_w      = (const float*)d_in[6];   // (E,E)
    const float* lin_b      = (const float*)d_in[7];   // (E)
    const float* in_proj_w  = (const float*)d_in[8];   // (3E,E)
    const float* in_proj_b  = (const float*)d_in[9];   // (3E)
    const float* out_proj_w = (const float*)d_in[10];  // (E,E)
    const float* out_proj_b = (const float*)d_in[11];  // (E)
    float* out = (float*)d_out;

    const int XSZ = Bb * Nn * Ee;                // 1,048,576
    const int ESZ = Bb * Nn * Nn;                // 4,194,304

    float* x_dst;
    float* e_dst;
    if (out_size >= XSZ + ESZ) { x_dst = out;      e_dst = out + XSZ; }
    else if (out_size == ESZ)  { x_dst = nullptr;  e_dst = out; }
    else                       { x_dst = out;      e_dst = nullptr; }

    // GAT
    k_wh<<<Bb * Nn, 256>>>(x, Wg, a1, a2);
    k_gat_attn<<<Bb * Nn, 256>>>(adj, e_dst);          // attn + fused e_out
    k_av<<<dim3(16, Bb, Hh), 256>>>(x, 0);             // hp + leaky + residual -> g_x1

    // norm 1: g_x1 -> g_tA (row), stats over g_tA
    k_rownorm<<<Bb * Nn, 256>>>(0);
    k_colpart<<<Bb * 16, 256>>>();
    k_colstats<<<Bb, 256>>>();

    // lin: colnorm(g_tA) @ lin_w.T -> g_tB   (colapply fused via normA)
    k_gemm<<<dim3(128, 4), 256>>>(nullptr, lin_w, lin_b, nullptr, 0, 0, 0, 1);

    // norm 2: g_tB -> g_tA (row), stats over g_tA
    k_rownorm<<<Bb * Nn, 256>>>(1);
    k_colpart<<<Bb * 16, 256>>>();
    k_colstats<<<Bb, 256>>>();

    // q, k from colnorm(g_tA) (fused); v from src (no norm)
    k_gemm<<<dim3(128, 4), 256>>>(nullptr, in_proj_w,             in_proj_b,       nullptr, 0, 1, 0, 1);
    k_gemm<<<dim3(128, 4), 256>>>(nullptr, in_proj_w + 256 * 256, in_proj_b + 256, nullptr, 0, 2, 0, 1);
    k_gemm<<<dim3(128, 4), 256>>>(src,     in_proj_w + 512 * 256, in_proj_b + 512, nullptr, 3, 3, 1, 0);

    // MHA: scores+softmax -> g_attn (reuse), then PV -> g_o
    k_qk<<<dim3(64, Bb, Hh), 256>>>();
    k_av<<<dim3(16, Bb, Hh), 256>>>(nullptr, 1);

    // out projection: g_o @ out_proj_w.T -> x_dst (or g_xout staging)
    k_gemm<<<dim3(128, 4), 256>>>(nullptr, out_proj_w, out_proj_b, x_dst, 2, 4, 0, 0);
}

// round 8
// speedup vs baseline: 1.2766x; 1.2766x over previous
#include <cuda_runtime.h>
#include <cuda_bf16.h>
#include <math.h>

#define Bb 4
#define Nn 1024
#define Ee 256
#define Hh 8
#define Dd 32

// ---------------- scratch (device globals; referenced ONLY inside kernels) ----
__device__ float g_Wh[(size_t)Hh*Bb*Nn*Dd];        // [h][b][n][d]  4MB
__device__ float g_s1[Hh*Bb*Nn];
__device__ float g_s2[Hh*Bb*Nn];
__device__ float g_attn[(size_t)Hh*Bb*Nn*Nn];      // 134MB (GAT attn, then MHA probs)
__device__ float g_x1[Bb*Nn*Ee];                   // GAT residual output
__device__ float g_tA[Bb*Nn*Ee];
__device__ float g_tB[Bb*Nn*Ee];
__device__ float g_q[Bb*Nn*Ee];
__device__ float g_k[Bb*Nn*Ee];
__device__ float g_v[Bb*Nn*Ee];
__device__ float g_o[Bb*Nn*Ee];
__device__ float g_eout[(size_t)Bb*Nn*Nn];         // e_out staging
__device__ float g_xout[Bb*Nn*Ee];                 // x staging
__device__ float g_psum[64*Ee];
__device__ float g_psq [64*Ee];
__device__ float g_cmean[Bb*Ee];
__device__ float g_crstd[Bb*Ee];

// ---------------- helpers ----------------
__device__ __forceinline__ float blockReduceSum(float v, float* sm) {
    sm[threadIdx.x] = v; __syncthreads();
    #pragma unroll
    for (int s = 128; s > 0; s >>= 1) {
        if (threadIdx.x < s) sm[threadIdx.x] += sm[threadIdx.x + s];
        __syncthreads();
    }
    float r = sm[0]; __syncthreads();
    return r;
}
// packed fp32x2 fma: acc.{lo,hi} += a.{lo,hi} * b.{lo,hi}   (FFMA2 on sm_103a)
__device__ __forceinline__ void ffma2(unsigned long long& acc,
                                      unsigned long long a, unsigned long long b) {
    asm("fma.rn.f32x2 %0, %1, %2, %0;" : "+l"(acc) : "l"(a), "l"(b));
}
__device__ __forceinline__ unsigned long long dup2(float x) {
    unsigned long long r;
    asm("mov.b64 %0, {%1, %1};" : "=l"(r) : "f"(x));
    return r;
}
__device__ __forceinline__ float f2lo(unsigned long long p) {
    return __uint_as_float((unsigned)(p & 0xffffffffu));
}
__device__ __forceinline__ float f2hi(unsigned long long p) {
    return __uint_as_float((unsigned)(p >> 32));
}
__device__ __forceinline__ float f2sum(unsigned long long p) { return f2lo(p) + f2hi(p); }

// ---------------- K1: Wh = x @ Wg (per head), s1/s2 reductions ----------------
__global__ void k_wh(const float* __restrict__ x, const float* __restrict__ Wg,
                     const float* __restrict__ a1, const float* __restrict__ a2) {
    int bn = blockIdx.x;              // b*N + n
    int b = bn >> 10, n = bn & 1023;
    int h = threadIdx.x >> 5, d = threadIdx.x & 31;
    __shared__ float xs[256];
    xs[threadIdx.x] = x[bn * 256 + threadIdx.x];
    __syncthreads();
    float acc = 0.f;
    const float* wp = Wg + h * 8192 + d;   // Wg[h][f][d]
    #pragma unroll 8
    for (int f = 0; f < 256; f++) acc = fmaf(xs[f], wp[f * 32], acc);
    g_Wh[((size_t)(h * Bb + b) * Nn + n) * 32 + d] = acc;
    float v1 = acc * a1[h * 32 + d];
    float v2 = acc * a2[h * 32 + d];
    #pragma unroll
    for (int o = 16; o > 0; o >>= 1) {
        v1 += __shfl_down_sync(0xffffffffu, v1, o);
        v2 += __shfl_down_sync(0xffffffffu, v2, o);
    }
    if (d == 0) {
        g_s1[(h * Bb + b) * Nn + n] = v1;
        g_s2[(h * Bb + b) * Nn + n] = v2;
    }
}

// ---------------- K2: GAT attention, warp-per-head, fused e_out ----------------
// grid = B*N, block = 256 (8 warps = 8 heads). adj staged in smem once.
__global__ void k_gat_attn(const int* __restrict__ adj, float* __restrict__ eout_dst) {
    __shared__ float esum[1024];
    __shared__ int adjm[1024];
    int n = blockIdx.x & 1023;
    int b = blockIdx.x >> 10;
    int t = threadIdx.x, h = t >> 5, lane = t & 31;
    const int* ap = adj + (size_t)(b * Nn + n) * Nn;
    #pragma unroll
    for (int i = 0; i < 4; i++) {
        adjm[t + i * 256] = ap[t + i * 256];
        esum[t + i * 256] = 0.f;
    }
    __syncthreads();

    float s1v = g_s1[(h * Bb + b) * Nn + n];
    const float* s2p = g_s2 + (h * Bb + b) * Nn;
    float ev[32];
    float mx = -INFINITY;
    #pragma unroll
    for (int j = 0; j < 32; j++) {
        int m = j * 32 + lane;
        float e = s1v + s2p[m];
        e = e >= 0.f ? e : 0.1f * e;
        if (adjm[m] <= 0) e = -9e15f;
        ev[j] = e;
        mx = fmaxf(mx, e);
    }
    #pragma unroll
    for (int o = 16; o > 0; o >>= 1) mx = fmaxf(mx, __shfl_xor_sync(0xffffffffu, mx, o));
    float sum = 0.f;
    #pragma unroll
    for (int j = 0; j < 32; j++) { ev[j] = __expf(ev[j] - mx); sum += ev[j]; }
    #pragma unroll
    for (int o = 16; o > 0; o >>= 1) sum += __shfl_xor_sync(0xffffffffu, sum, o);
    float inv = 1.0f / sum;

    float* op = g_attn + (size_t)((h * Bb + b) * Nn + n) * Nn;
    #pragma unroll
    for (int j = 0; j < 32; j++) {
        float p = ev[j] * inv;
        op[j * 32 + lane] = p;
        atomicAdd(&esum[j * 32 + lane], p);
    }
    __syncthreads();
    float* dst = eout_dst ? eout_dst : g_eout;
    #pragma unroll
    for (int i = 0; i < 4; i++)
        dst[((size_t)b * Nn + n) * Nn + t + i * 256] = esum[t + i * 256] * 0.125f;
}

// ---------------- K4: AV GEMM: 64-row tile of P[1024x1024] @ V[1024x32] --------
// mode 0 (hp): B = g_Wh[h][b], epilogue leaky(0.01) + residual -> g_x1
// mode 1 (pv): B = g_v slice h -> g_o
// 128 threads; thread tile 4 rows (tr+16*rr) x 4 cols (tc+8*cc); f32x2 over k.
__global__ void k_av(const float* __restrict__ x, int mode) {
    __shared__ float As[64 * 34];   // [row][k]
    __shared__ float Ws[32 * 34];   // [d][m]  (k-major)
    int tile = blockIdx.x, b = blockIdx.y, h = blockIdx.z;
    int t = threadIdx.x;
    int tr = t >> 3, tc = t & 7;
    int n0 = tile * 64;
    const float* ap  = g_attn + ((size_t)(h * Bb + b) * Nn + n0) * Nn;
    const float* whp = g_Wh + (size_t)(h * Bb + b) * Nn * 32;

    unsigned long long acc2[4][4];
    #pragma unroll
    for (int r = 0; r < 4; r++)
        #pragma unroll
        for (int c = 0; c < 4; c++) acc2[r][c] = 0ull;

    for (int ch = 0; ch < 32; ch++) {
        int m0 = ch * 32;
        #pragma unroll
        for (int i = 0; i < 16; i++) {
            int idx = i * 128 + t;
            int row = idx >> 5, k = idx & 31;
            As[row * 34 + k] = ap[(size_t)row * Nn + m0 + k];
        }
        #pragma unroll
        for (int i = 0; i < 8; i++) {
            int idx = i * 128 + t;
            int m = idx >> 5, d = idx & 31;
            Ws[d * 34 + m] = (mode == 0)
                ? whp[(m0 + m) * 32 + d]
                : g_v[((size_t)b * Nn + m0 + m) * 256 + h * 32 + d];
        }
        __syncthreads();
        #pragma unroll
        for (int k2 = 0; k2 < 16; k2++) {
            unsigned long long a2[4], w2[4];
            #pragma unroll
            for (int r = 0; r < 4; r++)
                a2[r] = *(const unsigned long long*)&As[(tr + r * 16) * 34 + 2 * k2];
            #pragma unroll
            for (int c = 0; c < 4; c++)
                w2[c] = *(const unsigned long long*)&Ws[(tc + c * 8) * 34 + 2 * k2];
            #pragma unroll
            for (int r = 0; r < 4; r++)
                #pragma unroll
                for (int c = 0; c < 4; c++)
                    ffma2(acc2[r][c], a2[r], w2[c]);
        }
        __syncthreads();
    }
    #pragma unroll
    for (int r = 0; r < 4; r++) {
        int n = n0 + tr + r * 16;
        #pragma unroll
        for (int c = 0; c < 4; c++) {
            float v = f2sum(acc2[r][c]);
            int idx = (b * Nn + n) * 256 + h * 32 + tc + c * 8;
            if (mode == 0) {
                v = v >= 0.f ? v : 0.01f * v;
                g_x1[idx] = x[idx] + v;
            } else {
                g_o[idx] = v;
            }
        }
    }
}

// ---------------- K5: row norm (_cnorm axis=2), ddof=1 ----------------
// sel=0: g_x1 -> g_tA ; sel=1: g_tB -> g_tA
__global__ void k_rownorm(int sel) {
    __shared__ float sm[256];
    const float* in = sel ? g_tB : g_x1;
    float* out = g_tA;
    int bn = blockIdx.x, t = threadIdx.x;
    float v = in[bn * 256 + t];
    float mean = blockReduceSum(v, sm) * (1.0f / 256.0f);
    float dd = v - mean;
    float var = blockReduceSum(dd * dd, sm) * (1.0f / 255.0f);
    out[bn * 256 + t] = dd / (sqrtf(var) + 1e-6f);
}

// ---------------- K6: column norm stats (over g_tA), split reduction ----------
__global__ void k_colpart() {
    int b = blockIdx.x >> 4, tl = blockIdx.x & 15;
    int e = threadIdx.x;
    float s = 0.f, sq = 0.f;
    const float* p = g_tA + ((size_t)b * Nn + tl * 64) * 256 + e;
    #pragma unroll 4
    for (int i = 0; i < 64; i++) {
        float v = p[i * 256];
        s += v; sq += v * v;
    }
    g_psum[blockIdx.x * 256 + e] = s;
    g_psq [blockIdx.x * 256 + e] = sq;
}
__global__ void k_colstats() {
    int b = blockIdx.x, e = threadIdx.x;
    float s = 0.f, sq = 0.f;
    #pragma unroll
    for (int t = 0; t < 16; t++) {
        s  += g_psum[(b * 16 + t) * 256 + e];
        sq += g_psq [(b * 16 + t) * 256 + e];
    }
    float mean = s * (1.0f / 1024.0f);
    float var = (sq - 1024.0f * mean * mean) * (1.0f / 1023.0f);
    var = fmaxf(var, 0.f);
    g_cmean[b * 256 + e] = mean;
    g_crstd[b * 256 + e] = 1.0f / (sqrtf(var) + 1e-6f);
}

// ---------------- K7: GEMM  C[M,256] = A'[M,256] @ W[256,256]^T + bias ---------
// 64x64 tile, 256 threads, thread tile 4x4 (bank-interleaved), f32x2 over k-pairs.
// normA: apply column-norm (A - cmean)*crstd during A load.
// asel: 0=g_tA, 2=g_o, 3=Aext (srcLayout applies)
// csel: 0=g_tB, 1=g_q, 2=g_k, 3=g_v, 4=Cext (fallback g_xout if null)
__global__ void k_gemm(const float* __restrict__ Aext, const float* __restrict__ W,
                       const float* __restrict__ bias, float* __restrict__ Cext,
                       int asel, int csel, int srcLayout, int normA) {
    __shared__ float As[64 * 66];
    __shared__ float Ws[64 * 66];
    const float* A = (asel == 0) ? g_tA : (asel == 2) ? g_o : Aext;
    float* C = (csel == 0) ? g_tB : (csel == 1) ? g_q : (csel == 2) ? g_k :
               (csel == 3) ? g_v : (Cext ? Cext : g_xout);
    int m0 = blockIdx.x * 64, i0 = blockIdx.y * 64;
    int t = threadIdx.x;
    int tr = t >> 4, ti = t & 15;
    unsigned long long acc2[4][4];
    #pragma unroll
    for (int a = 0; a < 4; a++)
        #pragma unroll
        for (int c = 0; c < 4; c++) acc2[a][c] = 0ull;

    for (int kt = 0; kt < 256; kt += 64) {
        #pragma unroll
        for (int l = 0; l < 16; l++) {
            int idx = t + l * 256;
            int r = idx >> 6, k = idx & 63;
            int bn = m0 + r;
            int abase;
            if (srcLayout) { int b = bn >> 10, n = bn & 1023; abase = (n * Bb + b) * 256; }
            else abase = bn * 256;
            float v = A[abase + kt + k];
            if (normA) {
                int b = bn >> 10;
                v = (v - g_cmean[b * 256 + kt + k]) * g_crstd[b * 256 + kt + k];
            }
            As[r * 66 + k] = v;
            Ws[r * 66 + k] = W[(i0 + r) * 256 + kt + k];
        }
        __syncthreads();
        #pragma unroll
        for (int k2 = 0; k2 < 32; k2++) {
            unsigned long long a2[4], w2[4];
            #pragma unroll
            for (int rr = 0; rr < 4; rr++)
                a2[rr] = *(const unsigned long long*)&As[(tr + rr * 16) * 66 + 2 * k2];
            #pragma unroll
            for (int ii = 0; ii < 4; ii++)
                w2[ii] = *(const unsigned long long*)&Ws[(ti + ii * 16) * 66 + 2 * k2];
            #pragma unroll
            for (int rr = 0; rr < 4; rr++)
                #pragma unroll
                for (int ii = 0; ii < 4; ii++)
                    ffma2(acc2[rr][ii], a2[rr], w2[ii]);
        }
        __syncthreads();
    }
    #pragma unroll
    for (int rr = 0; rr < 4; rr++)
        #pragma unroll
        for (int ii = 0; ii < 4; ii++)
            C[(m0 + tr + rr * 16) * 256 + i0 + ti + ii * 16] =
                f2sum(acc2[rr][ii]) + bias[i0 + ti + ii * 16];
}

// ---------------- K8: QK^T + fused softmax -> P (into g_attn) ------------------
// grid (64 panels of 16 q-rows, 4 b, 8 h), 256 threads; f32x2 over col pairs.
__global__ void k_qk() {
    __shared__ float Qs[16 * 33];    // [row][d]
    __shared__ float Ks[32 * 68];    // [d][col] pad 4
    int t = threadIdx.x;
    int b = blockIdx.y, h = blockIdx.z;
    int q0 = blockIdx.x * 16;
    int row = t >> 4, cg = t & 15;

    #pragma unroll
    for (int i = 0; i < 2; i++) {
        int idx = i * 256 + t;
        int r = idx >> 5, d = idx & 31;
        Qs[r * 33 + d] = g_q[((size_t)b * Nn + q0 + r) * 256 + h * 32 + d];
    }
    __syncthreads();

    float s[64];
    for (int kt = 0; kt < 16; kt++) {
        #pragma unroll
        for (int i = 0; i < 8; i++) {
            int idx = i * 256 + t;
            int col = idx >> 5, d = idx & 31;
            Ks[d * 68 + col] = g_k[((size_t)b * Nn + kt * 64 + col) * 256 + h * 32 + d];
        }
        __syncthreads();
        unsigned long long p0 = 0ull, p1 = 0ull;
        #pragma unroll
        for (int d = 0; d < 32; d++) {
            unsigned long long qq = dup2(Qs[row * 33 + d]);
            unsigned long long k01 = *(const unsigned long long*)&Ks[d * 68 + cg * 4];
            unsigned long long k23 = *(const unsigned long long*)&Ks[d * 68 + cg * 4 + 2];
            ffma2(p0, qq, k01);
            ffma2(p1, qq, k23);
        }
        s[kt * 4 + 0] = f2lo(p0); s[kt * 4 + 1] = f2hi(p0);
        s[kt * 4 + 2] = f2lo(p1); s[kt * 4 + 3] = f2hi(p1);
        __syncthreads();
    }

    const float scale = 0.17677669529663689f;  // 1/sqrt(32)
    float mx = -INFINITY;
    #pragma unroll
    for (int i = 0; i < 64; i++) { s[i] *= scale; mx = fmaxf(mx, s[i]); }
    #pragma unroll
    for (int o = 8; o > 0; o >>= 1) mx = fmaxf(mx, __shfl_xor_sync(0xffffffffu, mx, o));
    float sum = 0.f;
    #pragma unroll
    for (int i = 0; i < 64; i++) { s[i] = __expf(s[i] - mx); sum += s[i]; }
    #pragma unroll
    for (int o = 8; o > 0; o >>= 1) sum += __shfl_xor_sync(0xffffffffu, sum, o);
    float inv = 1.0f / sum;

    float* prow = g_attn + ((size_t)(h * Bb + b) * Nn + q0 + row) * Nn;
    #pragma unroll
    for (int kt = 0; kt < 16; kt++) {
        float4 v = make_float4(s[kt * 4] * inv, s[kt * 4 + 1] * inv,
                               s[kt * 4 + 2] * inv, s[kt * 4 + 3] * inv);
        *(float4*)&prow[kt * 64 + cg * 4] = v;
    }
}

// ---------------- launch ----------------
extern "C" void kernel_launch(void* const* d_in, const int* in_sizes, int n_in,
                              void* d_out, int out_size) {
    const float* x          = (const float*)d_in[0];   // (B,N,E)
    const float* src        = (const float*)d_in[1];   // (N,B,E)
    const int*   adj        = (const int*)  d_in[2];   // (B,N,N)
    const float* Wg         = (const float*)d_in[3];   // (H,E,D)
    const float* a1         = (const float*)d_in[4];   // (H,D)
    const float* a2         = (const float*)d_in[5];   // (H,D)
    const float* lin_w      = (const float*)d_in[6];   // (E,E)
    const float* lin_b      = (const float*)d_in[7];   // (E)
    const float* in_proj_w  = (const float*)d_in[8];   // (3E,E)
    const float* in_proj_b  = (const float*)d_in[9];   // (3E)
    const float* out_proj_w = (const float*)d_in[10];  // (E,E)
    const float* out_proj_b = (const float*)d_in[11];  // (E)
    float* out = (float*)d_out;

    const int XSZ = Bb * Nn * Ee;                // 1,048,576
    const int ESZ = Bb * Nn * Nn;                // 4,194,304

    float* x_dst;
    float* e_dst;
    if (out_size >= XSZ + ESZ) { x_dst = out;      e_dst = out + XSZ; }
    else if (out_size == ESZ)  { x_dst = nullptr;  e_dst = out; }
    else                       { x_dst = out;      e_dst = nullptr; }

    // GAT
    k_wh<<<Bb * Nn, 256>>>(x, Wg, a1, a2);
    k_gat_attn<<<Bb * Nn, 256>>>(adj, e_dst);          // warp-per-head, fused e_out
    k_av<<<dim3(16, Bb, Hh), 128>>>(x, 0);             // hp + leaky + residual -> g_x1

    // norm 1: g_x1 -> g_tA (row), stats over g_tA
    k_rownorm<<<Bb * Nn, 256>>>(0);
    k_colpart<<<Bb * 16, 256>>>();
    k_colstats<<<Bb, 256>>>();

    // lin: colnorm(g_tA) @ lin_w.T -> g_tB   (colapply fused via normA)
    k_gemm<<<dim3(64, 4), 256>>>(nullptr, lin_w, lin_b, nullptr, 0, 0, 0, 1);

    // norm 2: g_tB -> g_tA (row), stats over g_tA
    k_rownorm<<<Bb * Nn, 256>>>(1);
    k_colpart<<<Bb * 16, 256>>>();
    k_colstats<<<Bb, 256>>>();

    // q, k from colnorm(g_tA) (fused); v from src (no norm)
    k_gemm<<<dim3(64, 4), 256>>>(nullptr, in_proj_w,             in_proj_b,       nullptr, 0, 1, 0, 1);
    k_gemm<<<dim3(64, 4), 256>>>(nullptr, in_proj_w + 256 * 256, in_proj_b + 256, nullptr, 0, 2, 0, 1);
    k_gemm<<<dim3(64, 4), 256>>>(src,     in_proj_w + 512 * 256, in_proj_b + 512, nullptr, 3, 3, 1, 0);

    // MHA: scores+softmax -> g_attn (reuse), then PV -> g_o
    k_qk<<<dim3(64, Bb, Hh), 256>>>();
    k_av<<<dim3(16, Bb, Hh), 128>>>(nullptr, 1);

    // out projection: g_o @ out_proj_w.T -> x_dst (or g_xout staging)
    k_gemm<<<dim3(64, 4), 256>>>(nullptr, out_proj_w, out_proj_b, x_dst, 2, 4, 0, 0);
}

// round 9
// speedup vs baseline: 1.3621x; 1.0670x over previous
#include <cuda_runtime.h>
#include <cuda_bf16.h>
#include <math.h>

#define Bb 4
#define Nn 1024
#define Ee 256
#define Hh 8
#define Dd 32

// ---------------- scratch (device globals; referenced ONLY inside kernels) ----
__device__ float g_Wh[(size_t)Hh*Bb*Nn*Dd];        // [h][b][n][d]  4MB
__device__ float g_s1[Hh*Bb*Nn];
__device__ float g_s2[Hh*Bb*Nn];
__device__ float g_rmx[Hh*Bb*Nn];                  // GAT softmax row max
__device__ float g_rsm[Hh*Bb*Nn];                  // GAT softmax row sum
__device__ unsigned g_adjbits[Bb*Nn*32];           // packed adjacency
__device__ float g_x1[Bb*Nn*Ee];                   // GAT residual output
__device__ float g_tA[Bb*Nn*Ee];
__device__ float g_tB[Bb*Nn*Ee];
__device__ float g_q[Bb*Nn*Ee];
__device__ float g_k[Bb*Nn*Ee];
__device__ float g_v[Bb*Nn*Ee];
__device__ float g_o[Bb*Nn*Ee];
__device__ float g_eout[(size_t)Bb*Nn*Nn];         // e_out staging (only if unused output)
__device__ float g_xout[Bb*Nn*Ee];                 // x staging
__device__ float g_psum[64*Ee];
__device__ float g_psq [64*Ee];
__device__ float g_cmean[Bb*Ee];
__device__ float g_crstd[Bb*Ee];

// ---------------- helpers ----------------
__device__ __forceinline__ float blockReduceSum(float v, float* sm) {
    sm[threadIdx.x] = v; __syncthreads();
    #pragma unroll
    for (int s = 128; s > 0; s >>= 1) {
        if (threadIdx.x < s) sm[threadIdx.x] += sm[threadIdx.x + s];
        __syncthreads();
    }
    float r = sm[0]; __syncthreads();
    return r;
}
__device__ __forceinline__ void ffma2(unsigned long long& acc,
                                      unsigned long long a, unsigned long long b) {
    asm("fma.rn.f32x2 %0, %1, %2, %0;" : "+l"(acc) : "l"(a), "l"(b));
}
__device__ __forceinline__ void fmul2(unsigned long long& acc, unsigned long long s) {
    asm("mul.rn.f32x2 %0, %0, %1;" : "+l"(acc) : "l"(s));
}
__device__ __forceinline__ unsigned long long dup2(float x) {
    unsigned long long r;
    asm("mov.b64 %0, {%1, %1};" : "=l"(r) : "f"(x));
    return r;
}
__device__ __forceinline__ float f2sum(unsigned long long p) {
    return __uint_as_float((unsigned)(p & 0xffffffffu)) + __uint_as_float((unsigned)(p >> 32));
}

// ---------------- K0: pack adjacency into bitmasks ----------------
__global__ void k_adjpack(const int* __restrict__ adj) {
    int row = blockIdx.x;                 // b*N + n
    int w = threadIdx.x >> 5, lane = threadIdx.x & 31;
    #pragma unroll
    for (int i = 0; i < 4; i++) {
        int u = w * 4 + i;
        unsigned bit = adj[(size_t)row * Nn + u * 32 + lane] > 0 ? 1u : 0u;
        unsigned mask = __ballot_sync(0xffffffffu, bit);
        if (lane == 0) g_adjbits[row * 32 + u] = mask;
    }
}

// ---------------- K1: Wh = x @ Wg (per head), s1/s2 reductions ----------------
__global__ void k_wh(const float* __restrict__ x, const float* __restrict__ Wg,
                     const float* __restrict__ a1, const float* __restrict__ a2) {
    int bn = blockIdx.x;
    int b = bn >> 10, n = bn & 1023;
    int h = threadIdx.x >> 5, d = threadIdx.x & 31;
    __shared__ float xs[256];
    xs[threadIdx.x] = x[bn * 256 + threadIdx.x];
    __syncthreads();
    float acc = 0.f;
    const float* wp = Wg + h * 8192 + d;
    #pragma unroll 8
    for (int f = 0; f < 256; f++) acc = fmaf(xs[f], wp[f * 32], acc);
    g_Wh[((size_t)(h * Bb + b) * Nn + n) * 32 + d] = acc;
    float v1 = acc * a1[h * 32 + d];
    float v2 = acc * a2[h * 32 + d];
    #pragma unroll
    for (int o = 16; o > 0; o >>= 1) {
        v1 += __shfl_down_sync(0xffffffffu, v1, o);
        v2 += __shfl_down_sync(0xffffffffu, v2, o);
    }
    if (d == 0) {
        g_s1[(h * Bb + b) * Nn + n] = v1;
        g_s2[(h * Bb + b) * Nn + n] = v2;
    }
}

// ---------------- K2: GAT flash: scores->softmax->@Wh fused, no attn matrix ----
// grid (16 row-tiles, Bb, Hh), 128 threads.
// tr=t>>3 (4 rows each), ti=t&7 (8 score cols each / 4 PV d-cols each).
__global__ void k_gat_flash(const float* __restrict__ x) {
    __shared__ float Ws[32 * 66];    // [d][m] k-major Wh chunk
    __shared__ float Ps[64 * 66];    // P tile [row][m]
    __shared__ float s2s[64];
    __shared__ unsigned adjw[64 * 2];
    int tile = blockIdx.x, b = blockIdx.y, h = blockIdx.z;
    int t = threadIdx.x, tr = t >> 3, ti = t & 7;
    int n0 = tile * 64;
    int hb = h * Bb + b;
    const float* whp = g_Wh + (size_t)hb * Nn * 32;

    float s1r[4];
    #pragma unroll
    for (int r = 0; r < 4; r++) s1r[r] = g_s1[hb * Nn + n0 + tr * 4 + r];

    float m_run[4], l_run[4];
    unsigned long long acc2[4][4];
    #pragma unroll
    for (int r = 0; r < 4; r++) {
        m_run[r] = -1e30f; l_run[r] = 0.f;
        #pragma unroll
        for (int j = 0; j < 4; j++) acc2[r][j] = 0ull;
    }

    int ubase = ti >> 2;                 // which uint within chunk (constant/thread)
    int bshift = (ti & 3) * 8;           // bit offset base

    for (int ch = 0; ch < 16; ch++) {
        int m0 = ch * 64;
        // loads
        #pragma unroll
        for (int i = 0; i < 16; i++) {
            int idx = i * 128 + t;
            int m = idx >> 5, d = idx & 31;
            Ws[d * 66 + m] = whp[(m0 + m) * 32 + d];
        }
        if (t < 64) s2s[t] = g_s2[hb * Nn + m0 + t];
        { int rl = t >> 1, u = t & 1;
          adjw[rl * 2 + u] = g_adjbits[(size_t)(b * Nn + n0 + rl) * 32 + (m0 >> 5) + u]; }
        __syncthreads();

        float s2v[8];
        #pragma unroll
        for (int c = 0; c < 8; c++) s2v[c] = s2s[ti * 8 + c];
        unsigned aw[4];
        #pragma unroll
        for (int r = 0; r < 4; r++) aw[r] = adjw[(tr * 4 + r) * 2 + ubase];

        // pass 1: chunk max
        float cmax[4];
        #pragma unroll
        for (int r = 0; r < 4; r++) {
            float cm = -1e30f;
            #pragma unroll
            for (int c = 0; c < 8; c++) {
                float e = s1r[r] + s2v[c];
                e = e >= 0.f ? e : 0.1f * e;
                if (!((aw[r] >> (bshift + c)) & 1u)) e = -9e15f;
                cm = fmaxf(cm, e);
            }
            #pragma unroll
            for (int o = 1; o < 8; o <<= 1) cm = fmaxf(cm, __shfl_xor_sync(0xffffffffu, cm, o));
            cmax[r] = cm;
        }
        // online update + pass 2: exp + write P
        #pragma unroll
        for (int r = 0; r < 4; r++) {
            float m_new = fmaxf(m_run[r], cmax[r]);
            float sc = __expf(m_run[r] - m_new);
            m_run[r] = m_new;
            unsigned long long sc2 = dup2(sc);
            #pragma unroll
            for (int j = 0; j < 4; j++) fmul2(acc2[r][j], sc2);
            float rs = 0.f;
            #pragma unroll
            for (int c = 0; c < 8; c++) {
                float e = s1r[r] + s2v[c];
                e = e >= 0.f ? e : 0.1f * e;
                if (!((aw[r] >> (bshift + c)) & 1u)) e = -9e15f;
                float p = __expf(e - m_new);
                Ps[(tr * 4 + r) * 66 + ti * 8 + c] = p;
                rs += p;
            }
            #pragma unroll
            for (int o = 1; o < 8; o <<= 1) rs += __shfl_xor_sync(0xffffffffu, rs, o);
            l_run[r] = l_run[r] * sc + rs;
        }
        __syncthreads();
        // PV: acc[r][d] += sum_m P[r][m] * Wh[m][d], f32x2 over m pairs
        #pragma unroll
        for (int k2 = 0; k2 < 32; k2++) {
            unsigned long long a2[4], w2[4];
            #pragma unroll
            for (int r = 0; r < 4; r++)
                a2[r] = *(const unsigned long long*)&Ps[(tr * 4 + r) * 66 + 2 * k2];
            #pragma unroll
            for (int j = 0; j < 4; j++)
                w2[j] = *(const unsigned long long*)&Ws[(ti * 4 + j) * 66 + 2 * k2];
            #pragma unroll
            for (int r = 0; r < 4; r++)
                #pragma unroll
                for (int j = 0; j < 4; j++)
                    ffma2(acc2[r][j], a2[r], w2[j]);
        }
        __syncthreads();
    }

    // epilogue: normalize, leaky 0.01, residual
    #pragma unroll
    for (int r = 0; r < 4; r++) {
        int n = n0 + tr * 4 + r;
        float inv = 1.0f / l_run[r];
        if (ti == 0) {
            g_rmx[hb * Nn + n] = m_run[r];
            g_rsm[hb * Nn + n] = l_run[r];
        }
        #pragma unroll
        for (int j = 0; j < 4; j++) {
            float v = f2sum(acc2[r][j]) * inv;
            v = v >= 0.f ? v : 0.01f * v;
            int idx = (b * Nn + n) * 256 + h * 32 + ti * 4 + j;
            g_x1[idx] = x[idx] + v;
        }
    }
}

// ---------------- K3: e_out recompute from stats ----------------
// grid = B*N (4096) blocks, 256 threads, 4 m each.
__global__ void k_eout2(float* __restrict__ out) {
    __shared__ float s2all[8 * 1024];   // 32KB
    __shared__ unsigned adjw[32];
    __shared__ float mxs[8], invs[8], s1s[8];
    int n = blockIdx.x & 1023;
    int b = blockIdx.x >> 10;
    int t = threadIdx.x;
    #pragma unroll
    for (int i = 0; i < 32; i++) {
        int idx = i * 256 + t;
        s2all[idx] = g_s2[((idx >> 10) * Bb + b) * Nn + (idx & 1023)];
    }
    if (t < 32) adjw[t] = g_adjbits[(size_t)(b * Nn + n) * 32 + t];
    if (t < 8) {
        int hb = t * Bb + b;
        mxs[t]  = g_rmx[hb * Nn + n];
        invs[t] = 1.0f / g_rsm[hb * Nn + n];
        s1s[t]  = g_s1[hb * Nn + n];
    }
    __syncthreads();
    float* dst = out ? out : g_eout;
    #pragma unroll
    for (int i = 0; i < 4; i++) {
        int m = t + i * 256;
        unsigned bit = (adjw[m >> 5] >> (m & 31)) & 1u;
        float acc = 0.f;
        #pragma unroll
        for (int h = 0; h < 8; h++) {
            float e = s1s[h] + s2all[h * 1024 + m];
            e = e >= 0.f ? e : 0.1f * e;
            if (!bit) e = -9e15f;
            acc += __expf(e - mxs[h]) * invs[h];
        }
        dst[((size_t)b * Nn + n) * Nn + m] = acc * 0.125f;
    }
}

// ---------------- K5: row norm (_cnorm axis=2), ddof=1 ----------------
__global__ void k_rownorm(int sel) {
    __shared__ float sm[256];
    const float* in = sel ? g_tB : g_x1;
    float* out = g_tA;
    int bn = blockIdx.x, t = threadIdx.x;
    float v = in[bn * 256 + t];
    float mean = blockReduceSum(v, sm) * (1.0f / 256.0f);
    float dd = v - mean;
    float var = blockReduceSum(dd * dd, sm) * (1.0f / 255.0f);
    out[bn * 256 + t] = dd / (sqrtf(var) + 1e-6f);
}

// ---------------- K6: column norm stats (over g_tA) ----------------
__global__ void k_colpart() {
    int b = blockIdx.x >> 4, tl = blockIdx.x & 15;
    int e = threadIdx.x;
    float s = 0.f, sq = 0.f;
    const float* p = g_tA + ((size_t)b * Nn + tl * 64) * 256 + e;
    #pragma unroll 4
    for (int i = 0; i < 64; i++) {
        float v = p[i * 256];
        s += v; sq += v * v;
    }
    g_psum[blockIdx.x * 256 + e] = s;
    g_psq [blockIdx.x * 256 + e] = sq;
}
__global__ void k_colstats() {
    int b = blockIdx.x, e = threadIdx.x;
    float s = 0.f, sq = 0.f;
    #pragma unroll
    for (int t = 0; t < 16; t++) {
        s  += g_psum[(b * 16 + t) * 256 + e];
        sq += g_psq [(b * 16 + t) * 256 + e];
    }
    float mean = s * (1.0f / 1024.0f);
    float var = (sq - 1024.0f * mean * mean) * (1.0f / 1023.0f);
    var = fmaxf(var, 0.f);
    g_cmean[b * 256 + e] = mean;
    g_crstd[b * 256 + e] = 1.0f / (sqrtf(var) + 1e-6f);
}

// ---------------- K7: GEMM  C[M,256] = A'[M,256] @ W[256,256]^T + bias ---------
__global__ void k_gemm(const float* __restrict__ Aext, const float* __restrict__ W,
                       const float* __restrict__ bias, float* __restrict__ Cext,
                       int asel, int csel, int srcLayout, int normA) {
    __shared__ float As[64 * 66];
    __shared__ float Ws[64 * 66];
    const float* A = (asel == 0) ? g_tA : (asel == 2) ? g_o : Aext;
    float* C = (csel == 0) ? g_tB : (csel == 1) ? g_q : (csel == 2) ? g_k :
               (csel == 3) ? g_v : (Cext ? Cext : g_xout);
    int m0 = blockIdx.x * 64, i0 = blockIdx.y * 64;
    int t = threadIdx.x;
    int tr = t >> 4, ti = t & 15;
    unsigned long long acc2[4][4];
    #pragma unroll
    for (int a = 0; a < 4; a++)
        #pragma unroll
        for (int c = 0; c < 4; c++) acc2[a][c] = 0ull;

    for (int kt = 0; kt < 256; kt += 64) {
        #pragma unroll
        for (int l = 0; l < 16; l++) {
            int idx = t + l * 256;
            int r = idx >> 6, k = idx & 63;
            int bn = m0 + r;
            int abase;
            if (srcLayout) { int b = bn >> 10, n = bn & 1023; abase = (n * Bb + b) * 256; }
            else abase = bn * 256;
            float v = A[abase + kt + k];
            if (normA) {
                int b = bn >> 10;
                v = (v - g_cmean[b * 256 + kt + k]) * g_crstd[b * 256 + kt + k];
            }
            As[r * 66 + k] = v;
            Ws[r * 66 + k] = W[(i0 + r) * 256 + kt + k];
        }
        __syncthreads();
        #pragma unroll
        for (int k2 = 0; k2 < 32; k2++) {
            unsigned long long a2[4], w2[4];
            #pragma unroll
            for (int rr = 0; rr < 4; rr++)
                a2[rr] = *(const unsigned long long*)&As[(tr + rr * 16) * 66 + 2 * k2];
            #pragma unroll
            for (int ii = 0; ii < 4; ii++)
                w2[ii] = *(const unsigned long long*)&Ws[(ti + ii * 16) * 66 + 2 * k2];
            #pragma unroll
            for (int rr = 0; rr < 4; rr++)
                #pragma unroll
                for (int ii = 0; ii < 4; ii++)
                    ffma2(acc2[rr][ii], a2[rr], w2[ii]);
        }
        __syncthreads();
    }
    #pragma unroll
    for (int rr = 0; rr < 4; rr++)
        #pragma unroll
        for (int ii = 0; ii < 4; ii++)
            C[(m0 + tr + rr * 16) * 256 + i0 + ti + ii * 16] =
                f2sum(acc2[rr][ii]) + bias[i0 + ti + ii * 16];
}

// ---------------- K8: MHA flash: QK^T -> online softmax -> @V, fused -----------
// grid (16 q-tiles, Bb, Hh), 128 threads. tr=t>>3 (4 rows), ti=t&7.
__global__ void k_mha_flash() {
    __shared__ float Qs[64 * 34];    // [r][d]
    __shared__ float Ks[64 * 34];    // [c][d]
    __shared__ float Vs[32 * 66];    // [d][m] k-major
    __shared__ float Ps[64 * 66];    // [row][m]
    int tile = blockIdx.x, b = blockIdx.y, h = blockIdx.z;
    int t = threadIdx.x, tr = t >> 3, ti = t & 7;
    int q0 = tile * 64;
    const float scale = 0.17677669529663689f;   // 1/sqrt(32)

    #pragma unroll
    for (int i = 0; i < 16; i++) {
        int idx = i * 128 + t;
        int r = idx >> 5, d = idx & 31;
        Qs[r * 34 + d] = g_q[((size_t)b * Nn + q0 + r) * 256 + h * 32 + d];
    }

    float m_run[4], l_run[4];
    unsigned long long acc2[4][4];
    #pragma unroll
    for (int r = 0; r < 4; r++) {
        m_run[r] = -1e30f; l_run[r] = 0.f;
        #pragma unroll
        for (int j = 0; j < 4; j++) acc2[r][j] = 0ull;
    }
    __syncthreads();

    for (int ch = 0; ch < 16; ch++) {
        int m0 = ch * 64;
        #pragma unroll
        for (int i = 0; i < 16; i++) {
            int idx = i * 128 + t;
            int c = idx >> 5, d = idx & 31;
            Ks[c * 34 + d] = g_k[((size_t)b * Nn + m0 + c) * 256 + h * 32 + d];
            Vs[d * 66 + c] = g_v[((size_t)b * Nn + m0 + c) * 256 + h * 32 + d];
        }
        __syncthreads();

        // QK: s[r][c], f32x2 along d
        unsigned long long sa[4][8];
        #pragma unroll
        for (int r = 0; r < 4; r++)
            #pragma unroll
            for (int c = 0; c < 8; c++) sa[r][c] = 0ull;
        #pragma unroll
        for (int d2 = 0; d2 < 16; d2++) {
            unsigned long long q2[4], k2[8];
            #pragma unroll
            for (int r = 0; r < 4; r++)
                q2[r] = *(const unsigned long long*)&Qs[(tr * 4 + r) * 34 + 2 * d2];
            #pragma unroll
            for (int c = 0; c < 8; c++)
                k2[c] = *(const unsigned long long*)&Ks[(ti * 8 + c) * 34 + 2 * d2];
            #pragma unroll
            for (int r = 0; r < 4; r++)
                #pragma unroll
                for (int c = 0; c < 8; c++)
                    ffma2(sa[r][c], q2[r], k2[c]);
        }
        // stats + P write
        #pragma unroll
        for (int r = 0; r < 4; r++) {
            float s[8];
            float cm = -1e30f;
            #pragma unroll
            for (int c = 0; c < 8; c++) {
                s[c] = f2sum(sa[r][c]) * scale;
                cm = fmaxf(cm, s[c]);
            }
            #pragma unroll
            for (int o = 1; o < 8; o <<= 1) cm = fmaxf(cm, __shfl_xor_sync(0xffffffffu, cm, o));
            float m_new = fmaxf(m_run[r], cm);
            float sc = __expf(m_run[r] - m_new);
            m_run[r] = m_new;
            unsigned long long sc2 = dup2(sc);
            #pragma unroll
            for (int j = 0; j < 4; j++) fmul2(acc2[r][j], sc2);
            float rs = 0.f;
            #pragma unroll
            for (int c = 0; c < 8; c++) {
                float p = __expf(s[c] - m_new);
                Ps[(tr * 4 + r) * 66 + ti * 8 + c] = p;
                rs += p;
            }
            #pragma unroll
            for (int o = 1; o < 8; o <<= 1) rs += __shfl_xor_sync(0xffffffffu, rs, o);
            l_run[r] = l_run[r] * sc + rs;
        }
        __syncthreads();
        // PV
        #pragma unroll
        for (int k2i = 0; k2i < 32; k2i++) {
            unsigned long long a2[4], w2[4];
            #pragma unroll
            for (int r = 0; r < 4; r++)
                a2[r] = *(const unsigned long long*)&Ps[(tr * 4 + r) * 66 + 2 * k2i];
            #pragma unroll
            for (int j = 0; j < 4; j++)
                w2[j] = *(const unsigned long long*)&Vs[(ti * 4 + j) * 66 + 2 * k2i];
            #pragma unroll
            for (int r = 0; r < 4; r++)
                #pragma unroll
                for (int j = 0; j < 4; j++)
                    ffma2(acc2[r][j], a2[r], w2[j]);
        }
        __syncthreads();
    }

    #pragma unroll
    for (int r = 0; r < 4; r++) {
        int n = q0 + tr * 4 + r;
        float inv = 1.0f / l_run[r];
        #pragma unroll
        for (int j = 0; j < 4; j++)
            g_o[((size_t)b * Nn + n) * 256 + h * 32 + ti * 4 + j] =
                f2sum(acc2[r][j]) * inv;
    }
}

// ---------------- launch ----------------
extern "C" void kernel_launch(void* const* d_in, const int* in_sizes, int n_in,
                              void* d_out, int out_size) {
    const float* x          = (const float*)d_in[0];
    const float* src        = (const float*)d_in[1];
    const int*   adj        = (const int*)  d_in[2];
    const float* Wg         = (const float*)d_in[3];
    const float* a1         = (const float*)d_in[4];
    const float* a2         = (const float*)d_in[5];
    const float* lin_w      = (const float*)d_in[6];
    const float* lin_b      = (const float*)d_in[7];
    const float* in_proj_w  = (const float*)d_in[8];
    const float* in_proj_b  = (const float*)d_in[9];
    const float* out_proj_w = (const float*)d_in[10];
    const float* out_proj_b = (const float*)d_in[11];
    float* out = (float*)d_out;

    const int XSZ = Bb * Nn * Ee;
    const int ESZ = Bb * Nn * Nn;

    float* x_dst;
    float* e_dst;
    if (out_size >= XSZ + ESZ) { x_dst = out;      e_dst = out + XSZ; }
    else if (out_size == ESZ)  { x_dst = nullptr;  e_dst = out; }
    else                       { x_dst = out;      e_dst = nullptr; }

    // GAT (flash, no attn materialization)
    k_adjpack<<<Bb * Nn, 256>>>(adj);
    k_wh<<<Bb * Nn, 256>>>(x, Wg, a1, a2);
    k_gat_flash<<<dim3(16, Bb, Hh), 128>>>(x);
    k_eout2<<<Bb * Nn, 256>>>(e_dst);

    // norm 1
    k_rownorm<<<Bb * Nn, 256>>>(0);
    k_colpart<<<Bb * 16, 256>>>();
    k_colstats<<<Bb, 256>>>();

    // lin (col-norm fused into A load)
    k_gemm<<<dim3(64, 4), 256>>>(nullptr, lin_w, lin_b, nullptr, 0, 0, 0, 1);

    // norm 2
    k_rownorm<<<Bb * Nn, 256>>>(1);
    k_colpart<<<Bb * 16, 256>>>();
    k_colstats<<<Bb, 256>>>();

    // q, k (col-norm fused); v from src
    k_gemm<<<dim3(64, 4), 256>>>(nullptr, in_proj_w,             in_proj_b,       nullptr, 0, 1, 0, 1);
    k_gemm<<<dim3(64, 4), 256>>>(nullptr, in_proj_w + 256 * 256, in_proj_b + 256, nullptr, 0, 2, 0, 1);
    k_gemm<<<dim3(64, 4), 256>>>(src,     in_proj_w + 512 * 256, in_proj_b + 512, nullptr, 3, 3, 1, 0);

    // MHA flash
    k_mha_flash<<<dim3(16, Bb, Hh), 128>>>();

    // out projection
    k_gemm<<<dim3(64, 4), 256>>>(nullptr, out_proj_w, out_proj_b, x_dst, 2, 4, 0, 0);
}